// round 1
// baseline (speedup 1.0000x reference)
#include <cuda_runtime.h>

#define W_      10
#define NQ      12
#define NSTATE  4096      // 2^12
#define BATCH   512
#define NIN     6
#define STAGES  2

// Precomputed rotation tables (global scratch; no allocation allowed).
// g_tab[(s*W + out)*1024 + g] = (cos(phi/2), sin(phi/2)),
//   phi = neuron_theta[s,out,10] + sum_i bit_i(g)*neuron_theta[s,out,i]
//   where bit (9-i) of g corresponds to workspace lane i.
__device__ float2 g_tab[STAGES * W_ * 1024];
__device__ float2 u_tab[STAGES * W_];

__global__ void precompute_kernel(const float* __restrict__ unitary_theta,
                                  const float* __restrict__ neuron_theta) {
    int idx = blockIdx.x * blockDim.x + threadIdx.x;
    if (idx < STAGES * W_ * 1024) {
        int g  = idx & 1023;
        int sn = idx >> 10;                       // s*W + out
        const float* th = neuron_theta + sn * (W_ + 1);
        float phi = th[W_];
        #pragma unroll
        for (int i = 0; i < W_; i++) {
            if ((g >> (9 - i)) & 1) phi += th[i];
        }
        float sv, cv;
        sincosf(phi * 0.5f, &sv, &cv);
        g_tab[idx] = make_float2(cv, sv);
    }
    if (idx < STAGES * W_) {
        float sv, cv;
        sincosf(unitary_theta[idx] * 0.5f, &sv, &cv);
        u_tab[idx] = make_float2(cv, sv);
    }
}

// One CTA per batch element; full 4096-float state lives in shared memory.
// Index convention: state index bit (11 - lane) = lane value.
//   lanes 0..9  : workspace (bits 11..2)
//   lane 10     : ancilla 0 (bit 1)
//   lane 11     : ancilla 1 (bit 0)
__global__ void __launch_bounds__(256, 4) sim_kernel(
    const float* __restrict__ psi_in,
    const int*   __restrict__ inp,
    float*       __restrict__ probs_out,
    float*       __restrict__ psi_out)
{
    __shared__ float st[NSTATE];
    __shared__ float red[256];

    const int b   = blockIdx.x;
    const int tid = threadIdx.x;

    // BitFlip layer as an XOR permutation on load (mask bits all >= 6,
    // so float4 granularity is preserved).
    int mask = 0;
    #pragma unroll
    for (int l = 0; l < NIN; l++) mask |= (inp[l] & 1) << (11 - l);
    const int mask4 = mask >> 2;

    const float4* in4 = (const float4*)(psi_in + (size_t)b * NSTATE);
    #pragma unroll
    for (int j = 0; j < 4; j++) {
        int i = tid + 256 * j;
        float4 v = in4[i ^ mask4];
        *(float4*)&st[i << 2] = v;
    }
    __syncthreads();

    for (int s = 0; s < STAGES; s++) {
        // ---- Unitary layer: RY(theta[s,i]) on lanes 0..9, fused pairwise.
        // Lanes (2i, 2i+1) occupy adjacent bits (p+1, p), p = 10 - 2i.
        #pragma unroll
        for (int i = 0; i < 5; i++) {
            const int p = 10 - 2 * i;
            const float2 cA = u_tab[s * W_ + 2 * i];      // lane 2i   -> bit p+1
            const float2 cB = u_tab[s * W_ + 2 * i + 1];  // lane 2i+1 -> bit p
            #pragma unroll
            for (int j = 0; j < 4; j++) {
                int g = tid + 256 * j;
                int base = (g & ((1 << p) - 1)) | ((g >> p) << (p + 2));
                float a0 = st[base];
                float a1 = st[base + (1 << p)];
                float a2 = st[base + (2 << p)];
                float a3 = st[base + (3 << p)];
                // RY on bit p+1: pairs (a0,a2),(a1,a3)
                float t0 = cA.x * a0 - cA.y * a2;
                float t2 = cA.y * a0 + cA.x * a2;
                float t1 = cA.x * a1 - cA.y * a3;
                float t3 = cA.y * a1 + cA.x * a3;
                // RY on bit p: pairs (t0,t1),(t2,t3)
                a0 = cB.x * t0 - cB.y * t1;
                a1 = cB.y * t0 + cB.x * t1;
                a2 = cB.x * t2 - cB.y * t3;
                a3 = cB.y * t2 + cB.x * t3;
                st[base]            = a0;
                st[base + (1 << p)] = a1;
                st[base + (2 << p)] = a2;
                st[base + (3 << p)] = a3;
            }
            __syncthreads();
        }

        // ---- Neuron layer: one neuron per workspace lane `out`.
        for (int out = 0; out < W_; out++) {
            const float2* __restrict__ tab = &g_tab[(s * W_ + out) << 10];
            float2 csr[4];

            // Pass A: per workspace-group (4 contiguous amps: bits {1,0}=(q10,q11)):
            //   RY(+phi) on q10, CRY(+pi) 10->11, RY(-phi) on q10.
            #pragma unroll
            for (int j = 0; j < 4; j++) {
                int g = tid + 256 * j;
                float2 cs = tab[g];
                csr[j] = cs;
                float4 a = *(float4*)&st[g << 2];
                float t0 = cs.x * a.x - cs.y * a.z;
                float t1 = cs.x * a.y - cs.y * a.w;
                float t2 = cs.y * a.x + cs.x * a.z;
                float t3 = cs.y * a.y + cs.x * a.w;
                float u2 = -t3, u3 = t2;              // CRY(+pi): b10=1 half
                a.x =  cs.x * t0 + cs.y * u2;
                a.y =  cs.x * t1 + cs.y * u3;
                a.z = -cs.y * t0 + cs.x * u2;
                a.w = -cs.y * t1 + cs.x * u3;
                *(float4*)&st[g << 2] = a;
            }
            __syncthreads();

            // Pass B: CRY(+pi, control = q11 (bit 0 == 1), target = lane `out`).
            // Pairs (x, x + 2^p), p = 11 - out, with bit p of x == 0, bit0 == 1:
            //   st[x] <- -st[y], st[y] <- st[x].
            {
                const int p = 11 - out;
                #pragma unroll
                for (int j = 0; j < 4; j++) {
                    int h = tid + 256 * j;
                    int low  = h & ((1 << (p - 1)) - 1);
                    int high = h >> (p - 1);
                    int x = 1 | (low << 1) | (high << (p + 1));
                    int y = x + (1 << p);
                    float ax = st[x], ay = st[y];
                    st[x] = -ay;
                    st[y] =  ax;
                }
            }
            __syncthreads();

            // Pass C: RY(+phi) on q10, CRY(-pi) 10->11, RY(-phi) on q10.
            // Same table values, still in registers.
            #pragma unroll
            for (int j = 0; j < 4; j++) {
                int g = tid + 256 * j;
                float2 cs = csr[j];
                float4 a = *(float4*)&st[g << 2];
                float t0 = cs.x * a.x - cs.y * a.z;
                float t1 = cs.x * a.y - cs.y * a.w;
                float t2 = cs.y * a.x + cs.x * a.z;
                float t3 = cs.y * a.y + cs.x * a.w;
                float u2 = t3, u3 = -t2;              // CRY(-pi)
                a.x =  cs.x * t0 + cs.y * u2;
                a.y =  cs.x * t1 + cs.y * u3;
                a.z = -cs.y * t0 + cs.x * u2;
                a.w = -cs.y * t1 + cs.x * u3;
                *(float4*)&st[g << 2] = a;
            }
            __syncthreads();
        }
    }

    // ---- probs: marginal over lanes 6..11 (= low 6 bits), i.e. sum of
    // squares over contiguous 64-blocks. probs[b][k], k = high 6 bits.
    {
        int k = tid >> 2, q = tid & 3;
        float acc = 0.f;
        int base = k * 64 + q * 16;
        #pragma unroll
        for (int j = 0; j < 16; j++) {
            float v = st[base + j];
            acc += v * v;
        }
        red[tid] = acc;
        __syncthreads();
        if (tid < 64) {
            float pr = red[4 * tid] + red[4 * tid + 1]
                     + red[4 * tid + 2] + red[4 * tid + 3];
            probs_out[b * 64 + tid] = pr;
        }
    }

    // ---- psi out
    float4* out4 = (float4*)(psi_out + (size_t)b * NSTATE);
    #pragma unroll
    for (int j = 0; j < 4; j++) {
        int i = tid + 256 * j;
        out4[i] = *(float4*)&st[i << 2];
    }
}

extern "C" void kernel_launch(void* const* d_in, const int* in_sizes, int n_in,
                              void* d_out, int out_size) {
    const float* psi = (const float*)d_in[0];
    const int*   inp = (const int*)d_in[1];
    const float* uth = (const float*)d_in[2];
    const float* nth = (const float*)d_in[3];
    float* out = (float*)d_out;

    // Output layout per reference return order: probs (512*64) then psi (512*4096).
    float* probs_out = out;
    float* psi_out   = out + BATCH * 64;

    precompute_kernel<<<(STAGES * W_ * 1024 + 255) / 256, 256>>>(uth, nth);
    sim_kernel<<<BATCH, 256>>>(psi, inp, probs_out, psi_out);
}

// round 2
// speedup vs baseline: 1.7471x; 1.7471x over previous
#include <cuda_runtime.h>

#define W_      10
#define NSTATE  4096
#define BATCH   512
#define NIN     6
#define STAGES  2

// g_tab[(s*W + out)*1024 + g] = (cos(phi/2), sin(phi/2)),
// phi = theta_bias + sum_i bit_i(g)*theta_i, g = state bits 11..2 (bit (9-i) <-> lane i)
__device__ float2 g_tab[STAGES * W_ * 1024];
__device__ float2 u_tab[STAGES * W_];

__global__ void precompute_kernel(const float* __restrict__ unitary_theta,
                                  const float* __restrict__ neuron_theta) {
    int idx = blockIdx.x * blockDim.x + threadIdx.x;
    if (idx < STAGES * W_ * 1024) {
        int g  = idx & 1023;
        int sn = idx >> 10;
        const float* th = neuron_theta + sn * (W_ + 1);
        float phi = th[W_];
        #pragma unroll
        for (int i = 0; i < W_; i++)
            if ((g >> (9 - i)) & 1) phi += th[i];
        float sv, cv;
        sincosf(phi * 0.5f, &sv, &cv);
        g_tab[idx] = make_float2(cv, sv);
    }
    if (idx < STAGES * W_) {
        float sv, cv;
        sincosf(unitary_theta[idx] * 0.5f, &sv, &cv);
        u_tab[idx] = make_float2(cv, sv);
    }
}

// Group transform: RY(+phi) on q10, CRY(sgn*pi) 10->11, RY(-phi) on q10,
// acting on 4 contiguous amps (bit1=q10, bit0=q11).
__device__ __forceinline__ void grp4(float4& a, float c, float s, float sgn) {
    float t0 = c * a.x - s * a.z;
    float t1 = c * a.y - s * a.w;
    float t2 = s * a.x + c * a.z;
    float t3 = s * a.y + c * a.w;
    float u2 = -sgn * t3, u3 = sgn * t2;
    a.x =  c * t0 + s * u2;
    a.y =  c * t1 + s * u3;
    a.z = -s * t0 + c * u2;
    a.w = -s * t1 + c * u3;
}

// Full neuron on 8 amps: A0 = target-bit=0 groups, A1 = target-bit=1.
__device__ __forceinline__ void neuron8(float4& A0, float4& A1, float2 cs0, float2 cs1) {
    grp4(A0, cs0.x, cs0.y, 1.f);
    grp4(A1, cs1.x, cs1.y, 1.f);
    // pass B: CRY(pi, q11 -> target bit): offsets l=1,3 (q11=1)
    float x1 = A0.y; A0.y = -A1.y; A1.y = x1;
    float x3 = A0.w; A0.w = -A1.w; A1.w = x3;
    grp4(A0, cs0.x, cs0.y, -1.f);
    grp4(A1, cs1.x, cs1.y, -1.f);
}

// RY on bit b of a 16-element register array (pairs (k, k+2^b), bit b of k == 0)
__device__ __forceinline__ void ry16(float r[16], int b, float2 cs) {
    #pragma unroll
    for (int k = 0; k < 16; k++) {
        if (!((k >> b) & 1)) {
            int k1 = k | (1 << b);
            float a0 = r[k], a1 = r[k1];
            r[k]  = cs.x * a0 - cs.y * a1;
            r[k1] = cs.y * a0 + cs.x * a1;
        }
    }
}

__device__ __forceinline__ void ry4pair(float4& a, float4& b, float2 cs) {
    float4 na, nb;
    na.x = cs.x * a.x - cs.y * b.x;  nb.x = cs.y * a.x + cs.x * b.x;
    na.y = cs.x * a.y - cs.y * b.y;  nb.y = cs.y * a.y + cs.x * b.y;
    na.z = cs.x * a.z - cs.y * b.z;  nb.z = cs.y * a.z + cs.x * b.z;
    na.w = cs.x * a.w - cs.y * b.w;  nb.w = cs.y * a.w + cs.x * b.w;
    a = na; b = nb;
}

// Neuron-pair sweep: neurons oA = 11-PA (target bit PA) then oA+1 (bit PA-1).
// Item owns bits {PA, PA-1, 1, 0} = 16 amps (4 float4 groups).
// float4/group index of group (j,i): gb + (j << (PA-2)) + (i << (PA-3)).
template <int PA>
__device__ __forceinline__ void neuron_pair(float* st,
                                            const float2* __restrict__ tabA,
                                            const float2* __restrict__ tabB,
                                            int t) {
    constexpr int PB = PA - 1;
    constexpr int LB = PB - 2;            // low free bits of group index
    float4* st4 = (float4*)st;
    const int low  = t & ((1 << LB) - 1);
    const int high = t >> LB;
    const int gb   = low | (high << (PA - 1));

    const int g00 = gb;
    const int g01 = gb + (1 << (PB - 2));
    const int g10 = gb + (1 << (PA - 2));
    const int g11 = g10 + (1 << (PB - 2));

    float4 q00 = st4[g00], q01 = st4[g01], q10 = st4[g10], q11 = st4[g11];

    // neuron oA: target dim j
    neuron8(q00, q10, tabA[g00], tabA[g10]);
    neuron8(q01, q11, tabA[g01], tabA[g11]);
    // neuron oA+1: target dim i
    neuron8(q00, q01, tabB[g00], tabB[g01]);
    neuron8(q10, q11, tabB[g10], tabB[g11]);

    st4[g00] = q00; st4[g01] = q01; st4[g10] = q10; st4[g11] = q11;
}

__global__ void __launch_bounds__(256, 3) sim_kernel(
    const float* __restrict__ psi_in,
    const int*   __restrict__ inp,
    float*       __restrict__ probs_out,
    float*       __restrict__ psi_out)
{
    __shared__ float st[NSTATE];
    __shared__ float red[256];

    const int b   = blockIdx.x;
    const int tid = threadIdx.x;

    int mask = 0;
    #pragma unroll
    for (int l = 0; l < NIN; l++) mask |= (inp[l] & 1) << (11 - l);

    #pragma unroll
    for (int s = 0; s < STAGES; s++) {
        const float2* ut = &u_tab[s * W_];

        // ---- P1: unitary lanes 0-3 (bits 11..8). amps = tid + k*256.
        {
            float r[16];
            if (s == 0) {
                const float* in = psi_in + (size_t)b * NSTATE;
                #pragma unroll
                for (int k = 0; k < 16; k++) r[k] = in[(tid + (k << 8)) ^ mask];
            } else {
                #pragma unroll
                for (int k = 0; k < 16; k++) r[k] = st[tid + (k << 8)];
            }
            ry16(r, 3, ut[0]); ry16(r, 2, ut[1]); ry16(r, 1, ut[2]); ry16(r, 0, ut[3]);
            #pragma unroll
            for (int k = 0; k < 16; k++) st[tid + (k << 8)] = r[k];
        }
        __syncthreads();

        // ---- P2: unitary lanes 4-7 (bits 7..4). amps = base + k*16.
        {
            const int base = (tid & 15) | ((tid >> 4) << 8);
            float r[16];
            #pragma unroll
            for (int k = 0; k < 16; k++) r[k] = st[base + (k << 4)];
            ry16(r, 3, ut[4]); ry16(r, 2, ut[5]); ry16(r, 1, ut[6]); ry16(r, 0, ut[7]);
            #pragma unroll
            for (int k = 0; k < 16; k++) st[base + (k << 4)] = r[k];
        }
        __syncthreads();

        // ---- P3: unitary lanes 8,9 (bits 3,2). 16 contiguous amps.
        {
            float4* st4 = (float4*)st;
            float4 v0 = st4[(tid << 2) + 0];
            float4 v1 = st4[(tid << 2) + 1];
            float4 v2 = st4[(tid << 2) + 2];
            float4 v3 = st4[(tid << 2) + 3];
            ry4pair(v0, v2, ut[8]);  ry4pair(v1, v3, ut[8]);   // bit 3 (lane 8)
            ry4pair(v0, v1, ut[9]);  ry4pair(v2, v3, ut[9]);   // bit 2 (lane 9)
            st4[(tid << 2) + 0] = v0;
            st4[(tid << 2) + 1] = v1;
            st4[(tid << 2) + 2] = v2;
            st4[(tid << 2) + 3] = v3;
        }
        __syncthreads();

        // ---- P4..P7: neuron pairs (0,1),(2,3),(4,5),(6,7)
        const float2* tb = &g_tab[(s * W_) << 10];
        neuron_pair<11>(st, tb + (0 << 10), tb + (1 << 10), tid); __syncthreads();
        neuron_pair<9 >(st, tb + (2 << 10), tb + (3 << 10), tid); __syncthreads();
        neuron_pair<7 >(st, tb + (4 << 10), tb + (5 << 10), tid); __syncthreads();
        neuron_pair<5 >(st, tb + (6 << 10), tb + (7 << 10), tid); __syncthreads();

        // ---- P8: neurons 8,9 (bits 3,2). Group idx == float4 idx == (tid<<2)+2j+i.
        {
            const float2* tabA = tb + (8 << 10);
            const float2* tabB = tb + (9 << 10);
            float4* st4 = (float4*)st;
            const int g0 = tid << 2;
            float4 q00 = st4[g0], q01 = st4[g0 + 1], q10 = st4[g0 + 2], q11 = st4[g0 + 3];

            neuron8(q00, q10, tabA[g0],     tabA[g0 + 2]);
            neuron8(q01, q11, tabA[g0 + 1], tabA[g0 + 3]);
            neuron8(q00, q01, tabB[g0],     tabB[g0 + 1]);
            neuron8(q10, q11, tabB[g0 + 2], tabB[g0 + 3]);

            if (s == STAGES - 1) {
                // write psi directly to global, accumulate prob partials
                float4* out4 = (float4*)(psi_out + (size_t)b * NSTATE);
                out4[g0] = q00; out4[g0 + 1] = q01; out4[g0 + 2] = q10; out4[g0 + 3] = q11;
                float ssq =
                    q00.x*q00.x + q00.y*q00.y + q00.z*q00.z + q00.w*q00.w +
                    q01.x*q01.x + q01.y*q01.y + q01.z*q01.z + q01.w*q01.w +
                    q10.x*q10.x + q10.y*q10.y + q10.z*q10.z + q10.w*q10.w +
                    q11.x*q11.x + q11.y*q11.y + q11.z*q11.z + q11.w*q11.w;
                red[tid] = ssq;
            } else {
                st4[g0] = q00; st4[g0 + 1] = q01; st4[g0 + 2] = q10; st4[g0 + 3] = q11;
            }
        }
        __syncthreads();
    }

    // ---- probs: bucket = bits 11..6 = tid>>2 of the 16-amp items
    if (tid < 64) {
        probs_out[b * 64 + tid] =
            red[4 * tid] + red[4 * tid + 1] + red[4 * tid + 2] + red[4 * tid + 3];
    }
}

extern "C" void kernel_launch(void* const* d_in, const int* in_sizes, int n_in,
                              void* d_out, int out_size) {
    const float* psi = (const float*)d_in[0];
    const int*   inp = (const int*)d_in[1];
    const float* uth = (const float*)d_in[2];
    const float* nth = (const float*)d_in[3];
    float* out = (float*)d_out;

    float* probs_out = out;
    float* psi_out   = out + BATCH * 64;

    precompute_kernel<<<(STAGES * W_ * 1024 + 255) / 256, 256>>>(uth, nth);
    sim_kernel<<<BATCH, 256>>>(psi, inp, probs_out, psi_out);
}